// round 16
// baseline (speedup 1.0000x reference)
#include <cuda_runtime.h>
#include <cuda_bf16.h>
#include <cstdint>

#define N_NODES 20000
#define N_EDGES 640000
#define K2_BLOCKS 296
#define K2_SMEM 85504

// ---------------- scratch (static device memory, no allocation) ----------------
__device__ float g_y0 [N_NODES * 32];
__device__ float g_y1t[N_NODES * 3 * 32];
__device__ float g_y2t[N_NODES * 5 * 32];
__device__ float g_sc [3 * N_NODES * 32];
__device__ float g_mid[N_NODES * 96];

__device__ __forceinline__ float silu_f(float x) {
    return __fdividef(x, 1.0f + __expf(-x));
}
__device__ __forceinline__ unsigned long long fma2(unsigned long long a,
                                                   unsigned long long b,
                                                   unsigned long long c) {
    unsigned long long d;
    asm("fma.rn.f32x2 %0, %1, %2, %3;" : "=l"(d) : "l"(a), "l"(b), "l"(c));
    return d;
}
__device__ __forceinline__ unsigned long long pack2(float lo, float hi) {
    unsigned long long p;
    asm("mov.b64 %0, {%1, %2};" : "=l"(p) : "f"(lo), "f"(hi));
    return p;
}
__device__ __forceinline__ uint32_t smem_u32(const void* p) {
    uint32_t a;
    asm("{ .reg .u64 t; cvta.to.shared.u64 t, %1; cvt.u32.u64 %0, t; }" : "=r"(a) : "l"(p));
    return a;
}

// ---------------- dummy no-op (profiler slot alignment) ----------------
__global__ void noop_kernel() {}

// ---------------- Kernel 1 (merged): k1a 2 nodes/warp | k1b 4 nodes/warp ----------------
__global__ void k1_kernel(const float* __restrict__ x,
                          const float* __restrict__ na,
                          const float* __restrict__ W1_0,
                          const float* __restrict__ W1_1,
                          const float* __restrict__ W1_2,
                          const float* __restrict__ scW)
{
    extern __shared__ __align__(16) float dsm[];
    int t = threadIdx.x;
    int lane = t & 31;
    int wrp  = t >> 5;

    if (blockIdx.x < 1250) {
        float* w0s = dsm;
        float* w1s = dsm + 1024;
        float* w2s = dsm + 2048;
        float* xs  = dsm + 3072 + wrp * 576;
        for (int i = t; i < 1024; i += blockDim.x) {
            w0s[i] = W1_0[i]; w1s[i] = W1_1[i]; w2s[i] = W1_2[i];
        }
        __syncthreads();

        int n0 = (blockIdx.x * 8 + wrp) * 2;

        {
            const float4* src = (const float4*)(x + (size_t)n0 * 288);
            float4* dst = (float4*)xs;
#pragma unroll
            for (int i = 0; i < 5; i++) {
                int idx = lane + i * 32;
                if (idx < 144) dst[idx] = __ldg(src + idx);
            }
        }
        __syncwarp();

        float x0a = xs[lane], x0b = xs[288 + lane];
        float x1a[3], x1b[3], x2a[5], x2b[5];
#pragma unroll
        for (int m = 0; m < 3; m++) {
            x1a[m] = xs[32 + lane * 3 + m];
            x1b[m] = xs[288 + 32 + lane * 3 + m];
        }
#pragma unroll
        for (int m = 0; m < 5; m++) {
            x2a[m] = xs[128 + lane * 5 + m];
            x2b[m] = xs[288 + 128 + lane * 5 + m];
        }

        float a0a = 0.f, a0b = 0.f;
        float a1a[3] = {0.f,0.f,0.f}, a1b[3] = {0.f,0.f,0.f};
        float a2a[5] = {0.f,0.f,0.f,0.f,0.f}, a2b[5] = {0.f,0.f,0.f,0.f,0.f};
#pragma unroll
        for (int u = 0; u < 32; u++) {
            float w0 = w0s[u * 32 + lane];
            float w1 = w1s[u * 32 + lane];
            float w2 = w2s[u * 32 + lane];
            a0a = fmaf(__shfl_sync(0xffffffffu, x0a, u), w0, a0a);
            a0b = fmaf(__shfl_sync(0xffffffffu, x0b, u), w0, a0b);
#pragma unroll
            for (int m = 0; m < 3; m++) {
                a1a[m] = fmaf(__shfl_sync(0xffffffffu, x1a[m], u), w1, a1a[m]);
                a1b[m] = fmaf(__shfl_sync(0xffffffffu, x1b[m], u), w1, a1b[m]);
            }
#pragma unroll
            for (int m = 0; m < 5; m++) {
                a2a[m] = fmaf(__shfl_sync(0xffffffffu, x2a[m], u), w2, a2a[m]);
                a2b[m] = fmaf(__shfl_sync(0xffffffffu, x2b[m], u), w2, a2b[m]);
            }
        }
        const float inv = 0.17677669529663687f;
        g_y0[n0 * 32 + lane]       = a0a * inv;
        g_y0[(n0 + 1) * 32 + lane] = a0b * inv;
#pragma unroll
        for (int m = 0; m < 3; m++) {
            g_y1t[(n0 * 3 + m) * 32 + lane]       = a1a[m] * inv;
            g_y1t[((n0 + 1) * 3 + m) * 32 + lane] = a1b[m] * inv;
        }
#pragma unroll
        for (int m = 0; m < 5; m++) {
            g_y2t[(n0 * 5 + m) * 32 + lane]       = a2a[m] * inv;
            g_y2t[((n0 + 1) * 5 + m) * 32 + lane] = a2b[m] * inv;
        }
#pragma unroll
        for (int j = 0; j < 3; j++) {
            g_mid[n0 * 96 + j * 32 + lane]       = 0.f;
            g_mid[(n0 + 1) * 96 + j * 32 + lane] = 0.f;
        }
    } else {
        float* s = dsm;
        for (int i = t; i < 12288; i += blockDim.x) s[i] = scW[i];
        __syncthreads();

        int n0 = ((blockIdx.x - 1250) * 8 + wrp) * 4;

        float x0[4], nav[4];
#pragma unroll
        for (int e = 0; e < 4; e++) {
            x0[e]  = x[(size_t)(n0 + e) * 288 + lane];
            nav[e] = (lane < 4) ? na[(n0 + e) * 4 + lane] : 0.f;
        }
        float nac[4][4];
#pragma unroll
        for (int e = 0; e < 4; e++)
#pragma unroll
            for (int v = 0; v < 4; v++)
                nac[e][v] = __shfl_sync(0xffffffffu, nav[e], v);

        float acc[4][3];
#pragma unroll
        for (int e = 0; e < 4; e++) { acc[e][0] = 0.f; acc[e][1] = 0.f; acc[e][2] = 0.f; }

#pragma unroll
        for (int u = 0; u < 32; u++) {
            float c[4][4];
#pragma unroll
            for (int e = 0; e < 4; e++) {
                float xu = __shfl_sync(0xffffffffu, x0[e], u);
#pragma unroll
                for (int v = 0; v < 4; v++) c[e][v] = xu * nac[e][v];
            }
#pragma unroll
            for (int h = 0; h < 3; h++) {
                const float* p = s + ((h * 32 + u) * 4) * 32 + lane;
                float p0 = p[0], p1 = p[32], p2 = p[64], p3 = p[96];
#pragma unroll
                for (int e = 0; e < 4; e++) {
                    acc[e][h] = fmaf(c[e][0], p0, acc[e][h]);
                    acc[e][h] = fmaf(c[e][1], p1, acc[e][h]);
                    acc[e][h] = fmaf(c[e][2], p2, acc[e][h]);
                    acc[e][h] = fmaf(c[e][3], p3, acc[e][h]);
                }
            }
        }
        const float invs = 0.08838834764831845f;
#pragma unroll
        for (int h = 0; h < 3; h++)
#pragma unroll
            for (int e = 0; e < 4; e++)
                g_sc[h * (N_NODES * 32) + (n0 + e) * 32 + lane] = acc[e][h] * invs;
    }
}

// ---------------- Kernel 2: HMMA, 32 edges/warp-iter (2 tiles share B fragments) ----------------
// smem: wm0s f32[512] @0 | Wb bf16[96][136] @2048 | union H/zb @28160 (4*12800) | ea @79360 (4*1536)
// per-warp union: H = 2 tiles x 16 rows x 272B (8704B); after GEMM, zb = 32 x 100 f32 (12800B)
__global__ void __launch_bounds__(128, 2) k2_kernel(const float* __restrict__ ee,
                          const float* __restrict__ ea,
                          const int*   __restrict__ eidx,
                          const float* __restrict__ Wm0,
                          const float* __restrict__ Wm1)
{
    extern __shared__ __align__(16) unsigned char smraw[];
    float*          wm0s = (float*)smraw;                          // [0, 2048)
    __nv_bfloat16*  Wb   = (__nv_bfloat16*)(smraw + 2048);         // [2048, 28160)
    float*          ea_s = (float*)(smraw + 79360);                // [79360, 85504)

    const uint32_t sb    = smem_u32(smraw);
    const uint32_t W_u32 = sb + 2048;
    const uint32_t U_u32 = sb + 28160;

    int tid  = threadIdx.x;
    int lane = tid & 31;
    int wrp  = tid >> 5;

    const float inv8 = 0.35355339059327373f;
    const float C0 = 0.125f * 0.17677669529663687f;
    const float C1 = C0 * 0.5773502691896258f;
    const float C2 = C0 * 0.4472135954999579f;

    for (int i = tid; i < 512; i += 128) wm0s[i] = Wm0[i] * inv8;
    for (int i = tid; i < 96 * 64; i += 128) {
        int n = i >> 6, k = i & 63;
        float Cn = (n < 32) ? C0 : (n < 64) ? C1 : C2;
        float w = Wm1[k * 96 + n] * Cn;
        __nv_bfloat16 hb = __float2bfloat16(w);
        Wb[n * 136 + k]      = hb;
        Wb[n * 136 + 64 + k] = __float2bfloat16(w - __bfloat162float(hb));
    }
    __syncthreads();

    float* ea_w = ea_s + wrp * 384;                // 32 edges x 12 floats
    const uint32_t Uw = U_u32 + (uint32_t)wrp * 12800;
    float* zb = (float*)(smraw + 28160 + wrp * 12800);

    int eloc = lane >> 1, half = lane & 1;
    const float* wp = wm0s + (half << 5);

    // per-tile ldmatrix bases (tile t at Uw + t*4352)
    const uint32_t a_off  = (uint32_t)(lane & 15) * 272 + (uint32_t)((lane >> 4) & 1) * 16;
    const uint32_t b_base = W_u32 + (uint32_t)(lane & 7) * 272 + (uint32_t)((lane >> 3) & 1) * 16
                                  + (uint32_t)((lane >> 4) & 1) * 128;
    const uint32_t hrow_off = (uint32_t)eloc * 272 + (uint32_t)half * 64;

    int wg = blockIdx.x * 4 + wrp;
    int nw = gridDim.x * 4;

    for (int g = wg; g < N_EDGES / 32; g += nw) {
        int base = g * 32;

        // ---- stage edge attrs for 32 edges (padded to 12 floats/edge) ----
        for (int i = lane; i < 288; i += 32) {
            int le = i / 9, c = i - le * 9;
            ea_w[le * 12 + c] = __ldg(ea + (size_t)base * 9 + i);
        }

        // ---- first MLP + silu + bf16 split, per tile ----
#pragma unroll
        for (int tile = 0; tile < 2; tile++) {
            const uint32_t hrow = Uw + (uint32_t)tile * 4352 + hrow_off;
            float ev[8];
            {
                const float4* p = (const float4*)(ee + (size_t)(base + tile * 16 + eloc) * 8);
                float4 va = __ldg(p), vb = __ldg(p + 1);
                ev[0]=va.x; ev[1]=va.y; ev[2]=va.z; ev[3]=va.w;
                ev[4]=vb.x; ev[5]=vb.y; ev[6]=vb.z; ev[7]=vb.w;
            }
            unsigned long long hacc[16];
#pragma unroll
            for (int j = 0; j < 16; j++) hacc[j] = 0ull;
#pragma unroll
            for (int k = 0; k < 8; k++) {
                unsigned long long ek2 = pack2(ev[k], ev[k]);
                const ulonglong2* q = (const ulonglong2*)(wp + (k << 6));
#pragma unroll
                for (int j = 0; j < 8; j++) {
                    ulonglong2 v = q[j];
                    hacc[2 * j]     = fma2(ek2, v.x, hacc[2 * j]);
                    hacc[2 * j + 1] = fma2(ek2, v.y, hacc[2 * j + 1]);
                }
            }
#pragma unroll
            for (int j = 0; j < 16; j += 2) {
                float s0, s1, s2, s3;
                asm("mov.b64 {%0,%1}, %2;" : "=f"(s0), "=f"(s1) : "l"(hacc[j]));
                asm("mov.b64 {%0,%1}, %2;" : "=f"(s2), "=f"(s3) : "l"(hacc[j + 1]));
                s0 = silu_f(s0); s1 = silu_f(s1); s2 = silu_f(s2); s3 = silu_f(s3);
                uint32_t hb0, hb1;
                asm("cvt.rn.bf16x2.f32 %0, %1, %2;" : "=r"(hb0) : "f"(s1), "f"(s0));
                asm("cvt.rn.bf16x2.f32 %0, %1, %2;" : "=r"(hb1) : "f"(s3), "f"(s2));
                float f0 = __uint_as_float(hb0 << 16);
                float f1 = __uint_as_float(hb0 & 0xFFFF0000u);
                float f2 = __uint_as_float(hb1 << 16);
                float f3 = __uint_as_float(hb1 & 0xFFFF0000u);
                uint32_t lb0, lb1;
                asm("cvt.rn.bf16x2.f32 %0, %1, %2;" : "=r"(lb0) : "f"(s1 - f1), "f"(s0 - f0));
                asm("cvt.rn.bf16x2.f32 %0, %1, %2;" : "=r"(lb1) : "f"(s3 - f3), "f"(s2 - f2));
                asm volatile("st.shared.v2.b32 [%0], {%1, %2};" :: "r"(hrow + j * 4), "r"(hb0), "r"(hb1) : "memory");
                asm volatile("st.shared.v2.b32 [%0], {%1, %2};" :: "r"(hrow + 128 + j * 4), "r"(lb0), "r"(lb1) : "memory");
            }
        }
        __syncwarp();

        // ---- GEMM: both tiles share each B fragment ----
        float acc0[48], acc1[48];
#pragma unroll
        for (int i = 0; i < 48; i++) { acc0[i] = 0.f; acc1[i] = 0.f; }
#pragma unroll
        for (int k = 0; k < 4; k++) {
            uint32_t a0h0, a0h1, a0h2, a0h3, a0l0, a0l1, a0l2, a0l3;
            uint32_t a1h0, a1h1, a1h2, a1h3, a1l0, a1l1, a1l2, a1l3;
            asm volatile("ldmatrix.sync.aligned.m8n8.x4.shared.b16 {%0,%1,%2,%3}, [%4];"
                         : "=r"(a0h0), "=r"(a0h1), "=r"(a0h2), "=r"(a0h3)
                         : "r"(Uw + a_off + k * 32));
            asm volatile("ldmatrix.sync.aligned.m8n8.x4.shared.b16 {%0,%1,%2,%3}, [%4];"
                         : "=r"(a0l0), "=r"(a0l1), "=r"(a0l2), "=r"(a0l3)
                         : "r"(Uw + a_off + 128 + k * 32));
            asm volatile("ldmatrix.sync.aligned.m8n8.x4.shared.b16 {%0,%1,%2,%3}, [%4];"
                         : "=r"(a1h0), "=r"(a1h1), "=r"(a1h2), "=r"(a1h3)
                         : "r"(Uw + 4352 + a_off + k * 32));
            asm volatile("ldmatrix.sync.aligned.m8n8.x4.shared.b16 {%0,%1,%2,%3}, [%4];"
                         : "=r"(a1l0), "=r"(a1l1), "=r"(a1l2), "=r"(a1l3)
                         : "r"(Uw + 4352 + a_off + 128 + k * 32));
#pragma unroll
            for (int n = 0; n < 12; n++) {
                uint32_t bh0, bh1, bl0, bl1;
                asm volatile("ldmatrix.sync.aligned.m8n8.x4.shared.b16 {%0,%1,%2,%3}, [%4];"
                             : "=r"(bh0), "=r"(bh1), "=r"(bl0), "=r"(bl1)
                             : "r"(b_base + (uint32_t)n * 2176 + k * 32));
                float* d0 = acc0 + n * 4;
                float* d1 = acc1 + n * 4;
                asm volatile("mma.sync.aligned.m16n8k16.row.col.f32.bf16.bf16.f32 "
                             "{%0,%1,%2,%3}, {%4,%5,%6,%7}, {%8,%9}, {%0,%1,%2,%3};"
                             : "+f"(d0[0]), "+f"(d0[1]), "+f"(d0[2]), "+f"(d0[3])
                             : "r"(a0h0), "r"(a0h1), "r"(a0h2), "r"(a0h3), "r"(bh0), "r"(bh1));
                asm volatile("mma.sync.aligned.m16n8k16.row.col.f32.bf16.bf16.f32 "
                             "{%0,%1,%2,%3}, {%4,%5,%6,%7}, {%8,%9}, {%0,%1,%2,%3};"
                             : "+f"(d0[0]), "+f"(d0[1]), "+f"(d0[2]), "+f"(d0[3])
                             : "r"(a0l0), "r"(a0l1), "r"(a0l2), "r"(a0l3), "r"(bh0), "r"(bh1));
                asm volatile("mma.sync.aligned.m16n8k16.row.col.f32.bf16.bf16.f32 "
                             "{%0,%1,%2,%3}, {%4,%5,%6,%7}, {%8,%9}, {%0,%1,%2,%3};"
                             : "+f"(d0[0]), "+f"(d0[1]), "+f"(d0[2]), "+f"(d0[3])
                             : "r"(a0h0), "r"(a0h1), "r"(a0h2), "r"(a0h3), "r"(bl0), "r"(bl1));
                asm volatile("mma.sync.aligned.m16n8k16.row.col.f32.bf16.bf16.f32 "
                             "{%0,%1,%2,%3}, {%4,%5,%6,%7}, {%8,%9}, {%0,%1,%2,%3};"
                             : "+f"(d1[0]), "+f"(d1[1]), "+f"(d1[2]), "+f"(d1[3])
                             : "r"(a1h0), "r"(a1h1), "r"(a1h2), "r"(a1h3), "r"(bh0), "r"(bh1));
                asm volatile("mma.sync.aligned.m16n8k16.row.col.f32.bf16.bf16.f32 "
                             "{%0,%1,%2,%3}, {%4,%5,%6,%7}, {%8,%9}, {%0,%1,%2,%3};"
                             : "+f"(d1[0]), "+f"(d1[1]), "+f"(d1[2]), "+f"(d1[3])
                             : "r"(a1l0), "r"(a1l1), "r"(a1l2), "r"(a1l3), "r"(bh0), "r"(bh1));
                asm volatile("mma.sync.aligned.m16n8k16.row.col.f32.bf16.bf16.f32 "
                             "{%0,%1,%2,%3}, {%4,%5,%6,%7}, {%8,%9}, {%0,%1,%2,%3};"
                             : "+f"(d1[0]), "+f"(d1[1]), "+f"(d1[2]), "+f"(d1[3])
                             : "r"(a1h0), "r"(a1h1), "r"(a1h2), "r"(a1h3), "r"(bl0), "r"(bl1));
            }
        }
        __syncwarp();   // H fully consumed; union region may be overwritten by zb

        // ---- gather contraction -> zb (aliases dead H region) ----
#pragma unroll 8
        for (int le = 0; le < 32; le++) {
            int s = __ldg(eidx + base + le);
            const float* eap = ea_w + le * 12;
            float4 qa = *(const float4*)eap;
            float4 qb = *(const float4*)(eap + 4);
            float  e8 = eap[8];

            float y0v = __ldg(g_y0 + (size_t)s * 32 + lane);
            float z1 = __ldg(g_y1t + (size_t)s * 96 + lane) * qa.y;
            z1 = fmaf(__ldg(g_y1t + (size_t)s * 96 + 32 + lane), qa.z, z1);
            z1 = fmaf(__ldg(g_y1t + (size_t)s * 96 + 64 + lane), qa.w, z1);
            float z2 = __ldg(g_y2t + (size_t)s * 160 + lane) * qb.x;
            z2 = fmaf(__ldg(g_y2t + (size_t)s * 160 + 32 + lane),  qb.y, z2);
            z2 = fmaf(__ldg(g_y2t + (size_t)s * 160 + 64 + lane),  qb.z, z2);
            z2 = fmaf(__ldg(g_y2t + (size_t)s * 160 + 96 + lane),  qb.w, z2);
            z2 = fmaf(__ldg(g_y2t + (size_t)s * 160 + 128 + lane), e8,   z2);

            zb[le * 100 + lane]      = y0v * qa.x;
            zb[le * 100 + 32 + lane] = z1;
            zb[le * 100 + 64 + lane] = z2;
        }
        __syncwarp();

        // ---- fused epilogue + scatter per tile ----
        {
            int q = lane >> 2, tg = lane & 3;
#pragma unroll
            for (int tile = 0; tile < 2; tile++) {
                const float* accT = tile ? acc1 : acc0;
                int eq  = tile * 16 + q;
                int dq  = __ldg(eidx + N_EDGES + base + eq);
                int dq8 = __ldg(eidx + N_EDGES + base + eq + 8);
                float* pq  = g_mid + (size_t)dq  * 96;
                float* pq8 = g_mid + (size_t)dq8 * 96;
                const float* zq  = zb + eq * 100;
                const float* zq8 = zb + (eq + 8) * 100;
#pragma unroll
                for (int n = 0; n < 12; n++) {
                    int col = n * 8 + tg * 2;
                    float2 za = *(const float2*)(zq  + col);
                    float2 zc = *(const float2*)(zq8 + col);
                    float m0 = accT[n * 4]     * za.x;
                    float m1 = accT[n * 4 + 1] * za.y;
                    float m2 = accT[n * 4 + 2] * zc.x;
                    float m3 = accT[n * 4 + 3] * zc.y;
                    asm volatile("red.global.add.v2.f32 [%0], {%1,%2};"
                                 :: "l"(pq + col), "f"(m0), "f"(m1) : "memory");
                    asm volatile("red.global.add.v2.f32 [%0], {%1,%2};"
                                 :: "l"(pq8 + col), "f"(m2), "f"(m3) : "memory");
                }
            }
        }
        __syncwarp();
    }
}

// ---------------- Kernel 3: node finalize (2 nodes per warp) ----------------
__global__ void k3_kernel(const float* __restrict__ l2_0,
                          const float* __restrict__ l2_1,
                          const float* __restrict__ l2_2,
                          float* __restrict__ out)
{
    __shared__ __align__(16) float s0t[32 * 36];
    __shared__ __align__(16) float s1t[32 * 68];
    __shared__ __align__(16) float s2t[32 * 100];
    __shared__ __align__(16) float mb[8][200];

    int t = threadIdx.x;
    for (int i = t; i < 1024; i += blockDim.x) { int k = i / 32, w = i % 32; s0t[w * 36 + k]  = l2_0[i]; }
    for (int i = t; i < 2048; i += blockDim.x) { int k = i / 32, w = i % 32; s1t[w * 68 + k]  = l2_1[i]; }
    for (int i = t; i < 3072; i += blockDim.x) { int k = i / 32, w = i % 32; s2t[w * 100 + k] = l2_2[i]; }
    __syncthreads();

    int lane = t & 31;
    int wrp  = t >> 5;
    int n0 = (blockIdx.x * 8 + wrp) * 2;
    float* m = mb[wrp];

    m[lane]       = g_mid[n0 * 96 + lane];
    m[32 + lane]  = g_mid[n0 * 96 + 32 + lane];
    m[64 + lane]  = g_mid[n0 * 96 + 64 + lane];
    m[96 + lane]  = g_mid[(n0 + 1) * 96 + lane];
    m[128 + lane] = g_mid[(n0 + 1) * 96 + 32 + lane];
    m[160 + lane] = g_mid[(n0 + 1) * 96 + 64 + lane];
    __syncwarp();

    unsigned long long A0a = 0ull, A1a = 0ull, A2a = 0ull, B2a = 0ull;
    unsigned long long A0b = 0ull, A1b = 0ull, A2b = 0ull, B2b = 0ull;
    const float* p0 = &s0t[lane * 36];
    const float* p1 = &s1t[lane * 68];
    const float* p2 = &s2t[lane * 100];
#pragma unroll
    for (int c = 0; c < 24; c++) {
        int k = c * 4;
        ulonglong2 ma = *(const ulonglong2*)&m[k];
        ulonglong2 mv = *(const ulonglong2*)&m[96 + k];
        ulonglong2 q2 = *(const ulonglong2*)(p2 + k);
        A2a = fma2(ma.x, q2.x, A2a);
        B2a = fma2(ma.y, q2.y, B2a);
        A2b = fma2(mv.x, q2.x, A2b);
        B2b = fma2(mv.y, q2.y, B2b);
        if (c < 16) {
            ulonglong2 q1 = *(const ulonglong2*)(p1 + k);
            A1a = fma2(ma.x, q1.x, A1a);
            A1a = fma2(ma.y, q1.y, A1a);
            A1b = fma2(mv.x, q1.x, A1b);
            A1b = fma2(mv.y, q1.y, A1b);
        }
        if (c < 8) {
            ulonglong2 q0 = *(const ulonglong2*)(p0 + k);
            A0a = fma2(ma.x, q0.x, A0a);
            A0a = fma2(ma.y, q0.y, A0a);
            A0b = fma2(mv.x, q0.x, A0b);
            A0b = fma2(mv.y, q0.y, A0b);
        }
    }

    const float i32 = 0.17677669529663687f;
    const float i64 = 0.125f;
    const float i96 = 0.10206207261596575f;

    float lo, hi, v0a, v1a, v2a, v0b, v1b, v2b;
    asm("mov.b64 {%0,%1}, %2;" : "=f"(lo), "=f"(hi) : "l"(A0a)); v0a = lo + hi;
    asm("mov.b64 {%0,%1}, %2;" : "=f"(lo), "=f"(hi) : "l"(A1a)); v1a = lo + hi;
    asm("mov.b64 {%0,%1}, %2;" : "=f"(lo), "=f"(hi) : "l"(A2a)); v2a = lo + hi;
    asm("mov.b64 {%0,%1}, %2;" : "=f"(lo), "=f"(hi) : "l"(B2a)); v2a += lo + hi;
    asm("mov.b64 {%0,%1}, %2;" : "=f"(lo), "=f"(hi) : "l"(A0b)); v0b = lo + hi;
    asm("mov.b64 {%0,%1}, %2;" : "=f"(lo), "=f"(hi) : "l"(A1b)); v1b = lo + hi;
    asm("mov.b64 {%0,%1}, %2;" : "=f"(lo), "=f"(hi) : "l"(A2b)); v2b = lo + hi;
    asm("mov.b64 {%0,%1}, %2;" : "=f"(lo), "=f"(hi) : "l"(B2b)); v2b += lo + hi;

    out[                    n0 * 32 + lane]       = silu_f(fmaf(v0a, i32, g_sc[                   n0 * 32 + lane]));
    out[N_NODES * 32      + n0 * 32 + lane]       = silu_f(fmaf(v1a, i64, g_sc[N_NODES * 32     + n0 * 32 + lane]));
    out[2 * N_NODES * 32  + n0 * 32 + lane]       = silu_f(fmaf(v2a, i96, g_sc[2 * N_NODES * 32 + n0 * 32 + lane]));
    out[                    (n0 + 1) * 32 + lane] = silu_f(fmaf(v0b, i32, g_sc[                   (n0 + 1) * 32 + lane]));
    out[N_NODES * 32      + (n0 + 1) * 32 + lane] = silu_f(fmaf(v1b, i64, g_sc[N_NODES * 32     + (n0 + 1) * 32 + lane]));
    out[2 * N_NODES * 32  + (n0 + 1) * 32 + lane] = silu_f(fmaf(v2b, i96, g_sc[2 * N_NODES * 32 + (n0 + 1) * 32 + lane]));
}

// ---------------- launch ----------------
extern "C" void kernel_launch(void* const* d_in, const int* in_sizes, int n_in,
                              void* d_out, int out_size)
{
    const float* x      = (const float*)d_in[0];
    const float* na     = (const float*)d_in[1];
    const float* ee     = (const float*)d_in[2];
    const float* ea     = (const float*)d_in[3];
    const int*   eidx   = (const int*)  d_in[4];
    const float* W1_0   = (const float*)d_in[5];
    const float* W1_1   = (const float*)d_in[6];
    const float* W1_2   = (const float*)d_in[7];
    const float* Wm0    = (const float*)d_in[8];
    const float* Wm1    = (const float*)d_in[9];
    const float* l2_0   = (const float*)d_in[10];
    const float* l2_1   = (const float*)d_in[11];
    const float* l2_2   = (const float*)d_in[12];
    const float* scW    = (const float*)d_in[13];
    float* out = (float*)d_out;

    cudaFuncSetAttribute(k1_kernel, cudaFuncAttributeMaxDynamicSharedMemorySize, 49152);
    cudaFuncSetAttribute(k2_kernel, cudaFuncAttributeMaxDynamicSharedMemorySize, K2_SMEM);

    // launch order chosen so k2 is the 4th kernel launch (profiler capture slot)
    k1_kernel<<<1875, 256, 49152>>>(x, na, W1_0, W1_1, W1_2, scW);
    noop_kernel<<<1, 32>>>();
    noop_kernel<<<1, 32>>>();
    k2_kernel<<<K2_BLOCKS, 128, K2_SMEM>>>(ee, ea, eidx, Wm0, Wm1);
    k3_kernel<<<1250, 256>>>(l2_0, l2_1, l2_2, out);
    (void)in_sizes; (void)n_in; (void)out_size;
}

// round 17
// speedup vs baseline: 1.0072x; 1.0072x over previous
#include <cuda_runtime.h>
#include <cuda_bf16.h>
#include <cstdint>

#define N_NODES 20000
#define N_EDGES 640000
#define K2_BLOCKS 444
#define K2_SMEM 69120

// ---------------- scratch (static device memory, no allocation) ----------------
__device__ float g_y0 [N_NODES * 32];
__device__ float g_y1t[N_NODES * 3 * 32];
__device__ float g_y2t[N_NODES * 5 * 32];
__device__ float g_sc [3 * N_NODES * 32];
__device__ float g_mid[N_NODES * 96];

__device__ __forceinline__ float silu_f(float x) {
    return __fdividef(x, 1.0f + __expf(-x));
}
__device__ __forceinline__ unsigned long long fma2(unsigned long long a,
                                                   unsigned long long b,
                                                   unsigned long long c) {
    unsigned long long d;
    asm("fma.rn.f32x2 %0, %1, %2, %3;" : "=l"(d) : "l"(a), "l"(b), "l"(c));
    return d;
}
__device__ __forceinline__ unsigned long long pack2(float lo, float hi) {
    unsigned long long p;
    asm("mov.b64 %0, {%1, %2};" : "=l"(p) : "f"(lo), "f"(hi));
    return p;
}
__device__ __forceinline__ uint32_t smem_u32(const void* p) {
    uint32_t a;
    asm("{ .reg .u64 t; cvta.to.shared.u64 t, %1; cvt.u32.u64 %0, t; }" : "=r"(a) : "l"(p));
    return a;
}

// ---------------- dummy no-op (profiler slot alignment) ----------------
__global__ void noop_kernel() {}

// ---------------- Kernel 1 (merged): k1a 2 nodes/warp | k1b 4 nodes/warp ----------------
__global__ void k1_kernel(const float* __restrict__ x,
                          const float* __restrict__ na,
                          const float* __restrict__ W1_0,
                          const float* __restrict__ W1_1,
                          const float* __restrict__ W1_2,
                          const float* __restrict__ scW)
{
    extern __shared__ __align__(16) float dsm[];
    int t = threadIdx.x;
    int lane = t & 31;
    int wrp  = t >> 5;

    if (blockIdx.x < 1250) {
        float* w0s = dsm;
        float* w1s = dsm + 1024;
        float* w2s = dsm + 2048;
        float* xs  = dsm + 3072 + wrp * 576;
        for (int i = t; i < 1024; i += blockDim.x) {
            w0s[i] = W1_0[i]; w1s[i] = W1_1[i]; w2s[i] = W1_2[i];
        }
        __syncthreads();

        int n0 = (blockIdx.x * 8 + wrp) * 2;

        {
            const float4* src = (const float4*)(x + (size_t)n0 * 288);
            float4* dst = (float4*)xs;
#pragma unroll
            for (int i = 0; i < 5; i++) {
                int idx = lane + i * 32;
                if (idx < 144) dst[idx] = __ldg(src + idx);
            }
        }
        __syncwarp();

        float x0a = xs[lane], x0b = xs[288 + lane];
        float x1a[3], x1b[3], x2a[5], x2b[5];
#pragma unroll
        for (int m = 0; m < 3; m++) {
            x1a[m] = xs[32 + lane * 3 + m];
            x1b[m] = xs[288 + 32 + lane * 3 + m];
        }
#pragma unroll
        for (int m = 0; m < 5; m++) {
            x2a[m] = xs[128 + lane * 5 + m];
            x2b[m] = xs[288 + 128 + lane * 5 + m];
        }

        float a0a = 0.f, a0b = 0.f;
        float a1a[3] = {0.f,0.f,0.f}, a1b[3] = {0.f,0.f,0.f};
        float a2a[5] = {0.f,0.f,0.f,0.f,0.f}, a2b[5] = {0.f,0.f,0.f,0.f,0.f};
#pragma unroll
        for (int u = 0; u < 32; u++) {
            float w0 = w0s[u * 32 + lane];
            float w1 = w1s[u * 32 + lane];
            float w2 = w2s[u * 32 + lane];
            a0a = fmaf(__shfl_sync(0xffffffffu, x0a, u), w0, a0a);
            a0b = fmaf(__shfl_sync(0xffffffffu, x0b, u), w0, a0b);
#pragma unroll
            for (int m = 0; m < 3; m++) {
                a1a[m] = fmaf(__shfl_sync(0xffffffffu, x1a[m], u), w1, a1a[m]);
                a1b[m] = fmaf(__shfl_sync(0xffffffffu, x1b[m], u), w1, a1b[m]);
            }
#pragma unroll
            for (int m = 0; m < 5; m++) {
                a2a[m] = fmaf(__shfl_sync(0xffffffffu, x2a[m], u), w2, a2a[m]);
                a2b[m] = fmaf(__shfl_sync(0xffffffffu, x2b[m], u), w2, a2b[m]);
            }
        }
        const float inv = 0.17677669529663687f;
        g_y0[n0 * 32 + lane]       = a0a * inv;
        g_y0[(n0 + 1) * 32 + lane] = a0b * inv;
#pragma unroll
        for (int m = 0; m < 3; m++) {
            g_y1t[(n0 * 3 + m) * 32 + lane]       = a1a[m] * inv;
            g_y1t[((n0 + 1) * 3 + m) * 32 + lane] = a1b[m] * inv;
        }
#pragma unroll
        for (int m = 0; m < 5; m++) {
            g_y2t[(n0 * 5 + m) * 32 + lane]       = a2a[m] * inv;
            g_y2t[((n0 + 1) * 5 + m) * 32 + lane] = a2b[m] * inv;
        }
#pragma unroll
        for (int j = 0; j < 3; j++) {
            g_mid[n0 * 96 + j * 32 + lane]       = 0.f;
            g_mid[(n0 + 1) * 96 + j * 32 + lane] = 0.f;
        }
    } else {
        float* s = dsm;
        for (int i = t; i < 12288; i += blockDim.x) s[i] = scW[i];
        __syncthreads();

        int n0 = ((blockIdx.x - 1250) * 8 + wrp) * 4;

        float x0[4], nav[4];
#pragma unroll
        for (int e = 0; e < 4; e++) {
            x0[e]  = x[(size_t)(n0 + e) * 288 + lane];
            nav[e] = (lane < 4) ? na[(n0 + e) * 4 + lane] : 0.f;
        }
        float nac[4][4];
#pragma unroll
        for (int e = 0; e < 4; e++)
#pragma unroll
            for (int v = 0; v < 4; v++)
                nac[e][v] = __shfl_sync(0xffffffffu, nav[e], v);

        float acc[4][3];
#pragma unroll
        for (int e = 0; e < 4; e++) { acc[e][0] = 0.f; acc[e][1] = 0.f; acc[e][2] = 0.f; }

#pragma unroll
        for (int u = 0; u < 32; u++) {
            float c[4][4];
#pragma unroll
            for (int e = 0; e < 4; e++) {
                float xu = __shfl_sync(0xffffffffu, x0[e], u);
#pragma unroll
                for (int v = 0; v < 4; v++) c[e][v] = xu * nac[e][v];
            }
#pragma unroll
            for (int h = 0; h < 3; h++) {
                const float* p = s + ((h * 32 + u) * 4) * 32 + lane;
                float p0 = p[0], p1 = p[32], p2 = p[64], p3 = p[96];
#pragma unroll
                for (int e = 0; e < 4; e++) {
                    acc[e][h] = fmaf(c[e][0], p0, acc[e][h]);
                    acc[e][h] = fmaf(c[e][1], p1, acc[e][h]);
                    acc[e][h] = fmaf(c[e][2], p2, acc[e][h]);
                    acc[e][h] = fmaf(c[e][3], p3, acc[e][h]);
                }
            }
        }
        const float invs = 0.08838834764831845f;
#pragma unroll
        for (int h = 0; h < 3; h++)
#pragma unroll
            for (int e = 0; e < 4; e++)
                g_sc[h * (N_NODES * 32) + (n0 + e) * 32 + lane] = acc[e][h] * invs;
    }
}

// ---------------- Kernel 2: HMMA, 32 edges/warp-iter (shared B), split tail, 3 blocks/SM ----------------
// smem: wm0s f32[512] @0 | Wb bf16[96][136] @2048 | union H/zb16 @28160 (4*8704) | ea @62976 (4*1536)
// per-warp union (8704B): H = 2 tiles x 16 x 272B during MLP/GEMM; then zb = 16 x 100 f32 per tile phase
__global__ void __launch_bounds__(128, 3) k2_kernel(const float* __restrict__ ee,
                          const float* __restrict__ ea,
                          const int*   __restrict__ eidx,
                          const float* __restrict__ Wm0,
                          const float* __restrict__ Wm1)
{
    extern __shared__ __align__(16) unsigned char smraw[];
    float*          wm0s = (float*)smraw;                          // [0, 2048)
    __nv_bfloat16*  Wb   = (__nv_bfloat16*)(smraw + 2048);         // [2048, 28160)
    float*          ea_s = (float*)(smraw + 62976);                // [62976, 69120)

    const uint32_t sb    = smem_u32(smraw);
    const uint32_t W_u32 = sb + 2048;
    const uint32_t U_u32 = sb + 28160;

    int tid  = threadIdx.x;
    int lane = tid & 31;
    int wrp  = tid >> 5;

    const float inv8 = 0.35355339059327373f;
    const float C0 = 0.125f * 0.17677669529663687f;
    const float C1 = C0 * 0.5773502691896258f;
    const float C2 = C0 * 0.4472135954999579f;

    for (int i = tid; i < 512; i += 128) wm0s[i] = Wm0[i] * inv8;
    for (int i = tid; i < 96 * 64; i += 128) {
        int n = i >> 6, k = i & 63;
        float Cn = (n < 32) ? C0 : (n < 64) ? C1 : C2;
        float w = Wm1[k * 96 + n] * Cn;
        __nv_bfloat16 hb = __float2bfloat16(w);
        Wb[n * 136 + k]      = hb;
        Wb[n * 136 + 64 + k] = __float2bfloat16(w - __bfloat162float(hb));
    }
    __syncthreads();

    float* ea_w = ea_s + wrp * 384;                   // 32 edges x 12 floats
    const uint32_t Uw = U_u32 + (uint32_t)wrp * 8704;
    float* zb = (float*)(smraw + 28160 + wrp * 8704); // 16 x 100 f32 (aliases dead H)

    int eloc = lane >> 1, half = lane & 1;
    const float* wp = wm0s + (half << 5);

    const uint32_t a_off  = (uint32_t)(lane & 15) * 272 + (uint32_t)((lane >> 4) & 1) * 16;
    const uint32_t b_base = W_u32 + (uint32_t)(lane & 7) * 272 + (uint32_t)((lane >> 3) & 1) * 16
                                  + (uint32_t)((lane >> 4) & 1) * 128;
    const uint32_t hrow_off = (uint32_t)eloc * 272 + (uint32_t)half * 64;

    int wg = blockIdx.x * 4 + wrp;
    int nw = gridDim.x * 4;

    for (int g = wg; g < N_EDGES / 32; g += nw) {
        int base = g * 32;

        // ---- stage edge attrs for 32 edges (padded to 12 floats/edge) ----
        for (int i = lane; i < 288; i += 32) {
            int le = i / 9, c = i - le * 9;
            ea_w[le * 12 + c] = __ldg(ea + (size_t)base * 9 + i);
        }

        // ---- first MLP + silu + bf16 split, per tile ----
#pragma unroll
        for (int tile = 0; tile < 2; tile++) {
            const uint32_t hrow = Uw + (uint32_t)tile * 4352 + hrow_off;
            float ev[8];
            {
                const float4* p = (const float4*)(ee + (size_t)(base + tile * 16 + eloc) * 8);
                float4 va = __ldg(p), vb = __ldg(p + 1);
                ev[0]=va.x; ev[1]=va.y; ev[2]=va.z; ev[3]=va.w;
                ev[4]=vb.x; ev[5]=vb.y; ev[6]=vb.z; ev[7]=vb.w;
            }
            unsigned long long hacc[16];
#pragma unroll
            for (int j = 0; j < 16; j++) hacc[j] = 0ull;
#pragma unroll
            for (int k = 0; k < 8; k++) {
                unsigned long long ek2 = pack2(ev[k], ev[k]);
                const ulonglong2* q = (const ulonglong2*)(wp + (k << 6));
#pragma unroll
                for (int j = 0; j < 8; j++) {
                    ulonglong2 v = q[j];
                    hacc[2 * j]     = fma2(ek2, v.x, hacc[2 * j]);
                    hacc[2 * j + 1] = fma2(ek2, v.y, hacc[2 * j + 1]);
                }
            }
#pragma unroll
            for (int j = 0; j < 16; j += 2) {
                float s0, s1, s2, s3;
                asm("mov.b64 {%0,%1}, %2;" : "=f"(s0), "=f"(s1) : "l"(hacc[j]));
                asm("mov.b64 {%0,%1}, %2;" : "=f"(s2), "=f"(s3) : "l"(hacc[j + 1]));
                s0 = silu_f(s0); s1 = silu_f(s1); s2 = silu_f(s2); s3 = silu_f(s3);
                uint32_t hb0, hb1;
                asm("cvt.rn.bf16x2.f32 %0, %1, %2;" : "=r"(hb0) : "f"(s1), "f"(s0));
                asm("cvt.rn.bf16x2.f32 %0, %1, %2;" : "=r"(hb1) : "f"(s3), "f"(s2));
                float f0 = __uint_as_float(hb0 << 16);
                float f1 = __uint_as_float(hb0 & 0xFFFF0000u);
                float f2 = __uint_as_float(hb1 << 16);
                float f3 = __uint_as_float(hb1 & 0xFFFF0000u);
                uint32_t lb0, lb1;
                asm("cvt.rn.bf16x2.f32 %0, %1, %2;" : "=r"(lb0) : "f"(s1 - f1), "f"(s0 - f0));
                asm("cvt.rn.bf16x2.f32 %0, %1, %2;" : "=r"(lb1) : "f"(s3 - f3), "f"(s2 - f2));
                asm volatile("st.shared.v2.b32 [%0], {%1, %2};" :: "r"(hrow + j * 4), "r"(hb0), "r"(hb1) : "memory");
                asm volatile("st.shared.v2.b32 [%0], {%1, %2};" :: "r"(hrow + 128 + j * 4), "r"(lb0), "r"(lb1) : "memory");
            }
        }
        __syncwarp();

        // ---- GEMM: both tiles share each B fragment ----
        float acc0[48], acc1[48];
#pragma unroll
        for (int i = 0; i < 48; i++) { acc0[i] = 0.f; acc1[i] = 0.f; }
#pragma unroll
        for (int k = 0; k < 4; k++) {
            uint32_t a0h0, a0h1, a0h2, a0h3, a0l0, a0l1, a0l2, a0l3;
            uint32_t a1h0, a1h1, a1h2, a1h3, a1l0, a1l1, a1l2, a1l3;
            asm volatile("ldmatrix.sync.aligned.m8n8.x4.shared.b16 {%0,%1,%2,%3}, [%4];"
                         : "=r"(a0h0), "=r"(a0h1), "=r"(a0h2), "=r"(a0h3)
                         : "r"(Uw + a_off + k * 32));
            asm volatile("ldmatrix.sync.aligned.m8n8.x4.shared.b16 {%0,%1,%2,%3}, [%4];"
                         : "=r"(a0l0), "=r"(a0l1), "=r"(a0l2), "=r"(a0l3)
                         : "r"(Uw + a_off + 128 + k * 32));
            asm volatile("ldmatrix.sync.aligned.m8n8.x4.shared.b16 {%0,%1,%2,%3}, [%4];"
                         : "=r"(a1h0), "=r"(a1h1), "=r"(a1h2), "=r"(a1h3)
                         : "r"(Uw + 4352 + a_off + k * 32));
            asm volatile("ldmatrix.sync.aligned.m8n8.x4.shared.b16 {%0,%1,%2,%3}, [%4];"
                         : "=r"(a1l0), "=r"(a1l1), "=r"(a1l2), "=r"(a1l3)
                         : "r"(Uw + 4352 + a_off + 128 + k * 32));
#pragma unroll
            for (int n = 0; n < 12; n++) {
                uint32_t bh0, bh1, bl0, bl1;
                asm volatile("ldmatrix.sync.aligned.m8n8.x4.shared.b16 {%0,%1,%2,%3}, [%4];"
                             : "=r"(bh0), "=r"(bh1), "=r"(bl0), "=r"(bl1)
                             : "r"(b_base + (uint32_t)n * 2176 + k * 32));
                float* d0 = acc0 + n * 4;
                float* d1 = acc1 + n * 4;
                asm volatile("mma.sync.aligned.m16n8k16.row.col.f32.bf16.bf16.f32 "
                             "{%0,%1,%2,%3}, {%4,%5,%6,%7}, {%8,%9}, {%0,%1,%2,%3};"
                             : "+f"(d0[0]), "+f"(d0[1]), "+f"(d0[2]), "+f"(d0[3])
                             : "r"(a0h0), "r"(a0h1), "r"(a0h2), "r"(a0h3), "r"(bh0), "r"(bh1));
                asm volatile("mma.sync.aligned.m16n8k16.row.col.f32.bf16.bf16.f32 "
                             "{%0,%1,%2,%3}, {%4,%5,%6,%7}, {%8,%9}, {%0,%1,%2,%3};"
                             : "+f"(d0[0]), "+f"(d0[1]), "+f"(d0[2]), "+f"(d0[3])
                             : "r"(a0l0), "r"(a0l1), "r"(a0l2), "r"(a0l3), "r"(bh0), "r"(bh1));
                asm volatile("mma.sync.aligned.m16n8k16.row.col.f32.bf16.bf16.f32 "
                             "{%0,%1,%2,%3}, {%4,%5,%6,%7}, {%8,%9}, {%0,%1,%2,%3};"
                             : "+f"(d0[0]), "+f"(d0[1]), "+f"(d0[2]), "+f"(d0[3])
                             : "r"(a0h0), "r"(a0h1), "r"(a0h2), "r"(a0h3), "r"(bl0), "r"(bl1));
                asm volatile("mma.sync.aligned.m16n8k16.row.col.f32.bf16.bf16.f32 "
                             "{%0,%1,%2,%3}, {%4,%5,%6,%7}, {%8,%9}, {%0,%1,%2,%3};"
                             : "+f"(d1[0]), "+f"(d1[1]), "+f"(d1[2]), "+f"(d1[3])
                             : "r"(a1h0), "r"(a1h1), "r"(a1h2), "r"(a1h3), "r"(bh0), "r"(bh1));
                asm volatile("mma.sync.aligned.m16n8k16.row.col.f32.bf16.bf16.f32 "
                             "{%0,%1,%2,%3}, {%4,%5,%6,%7}, {%8,%9}, {%0,%1,%2,%3};"
                             : "+f"(d1[0]), "+f"(d1[1]), "+f"(d1[2]), "+f"(d1[3])
                             : "r"(a1l0), "r"(a1l1), "r"(a1l2), "r"(a1l3), "r"(bh0), "r"(bh1));
                asm volatile("mma.sync.aligned.m16n8k16.row.col.f32.bf16.bf16.f32 "
                             "{%0,%1,%2,%3}, {%4,%5,%6,%7}, {%8,%9}, {%0,%1,%2,%3};"
                             : "+f"(d1[0]), "+f"(d1[1]), "+f"(d1[2]), "+f"(d1[3])
                             : "r"(a1h0), "r"(a1h1), "r"(a1h2), "r"(a1h3), "r"(bl0), "r"(bl1));
            }
        }
        __syncwarp();   // H fully consumed; union region reusable

        // ---- per-tile: gather -> zb (16 edges), then fused epilogue + scatter ----
#pragma unroll
        for (int tile = 0; tile < 2; tile++) {
            int tbase = base + tile * 16;
#pragma unroll 4
            for (int le = 0; le < 16; le++) {
                int s = __ldg(eidx + tbase + le);
                const float* eap = ea_w + (tile * 16 + le) * 12;
                float4 qa = *(const float4*)eap;
                float4 qb = *(const float4*)(eap + 4);
                float  e8 = eap[8];

                float y0v = __ldg(g_y0 + (size_t)s * 32 + lane);
                float z1 = __ldg(g_y1t + (size_t)s * 96 + lane) * qa.y;
                z1 = fmaf(__ldg(g_y1t + (size_t)s * 96 + 32 + lane), qa.z, z1);
                z1 = fmaf(__ldg(g_y1t + (size_t)s * 96 + 64 + lane), qa.w, z1);
                float z2 = __ldg(g_y2t + (size_t)s * 160 + lane) * qb.x;
                z2 = fmaf(__ldg(g_y2t + (size_t)s * 160 + 32 + lane),  qb.y, z2);
                z2 = fmaf(__ldg(g_y2t + (size_t)s * 160 + 64 + lane),  qb.z, z2);
                z2 = fmaf(__ldg(g_y2t + (size_t)s * 160 + 96 + lane),  qb.w, z2);
                z2 = fmaf(__ldg(g_y2t + (size_t)s * 160 + 128 + lane), e8,   z2);

                zb[le * 100 + lane]      = y0v * qa.x;
                zb[le * 100 + 32 + lane] = z1;
                zb[le * 100 + 64 + lane] = z2;
            }
            __syncwarp();

            {
                const float* accT = tile ? acc1 : acc0;
                int q = lane >> 2, tg = lane & 3;
                int dq  = __ldg(eidx + N_EDGES + tbase + q);
                int dq8 = __ldg(eidx + N_EDGES + tbase + q + 8);
                float* pq  = g_mid + (size_t)dq  * 96;
                float* pq8 = g_mid + (size_t)dq8 * 96;
                const float* zq  = zb + q * 100;
                const float* zq8 = zb + (q + 8) * 100;
#pragma unroll
                for (int n = 0; n < 12; n++) {
                    int col = n * 8 + tg * 2;
                    float2 za = *(const float2*)(zq  + col);
                    float2 zc = *(const float2*)(zq8 + col);
                    float m0 = accT[n * 4]     * za.x;
                    float m1 = accT[n * 4 + 1] * za.y;
                    float m2 = accT[n * 4 + 2] * zc.x;
                    float m3 = accT[n * 4 + 3] * zc.y;
                    asm volatile("red.global.add.v2.f32 [%0], {%1,%2};"
                                 :: "l"(pq + col), "f"(m0), "f"(m1) : "memory");
                    asm volatile("red.global.add.v2.f32 [%0], {%1,%2};"
                                 :: "l"(pq8 + col), "f"(m2), "f"(m3) : "memory");
                }
            }
            __syncwarp();
        }
    }
}

// ---------------- Kernel 3: node finalize (2 nodes per warp) ----------------
__global__ void k3_kernel(const float* __restrict__ l2_0,
                          const float* __restrict__ l2_1,
                          const float* __restrict__ l2_2,
                          float* __restrict__ out)
{
    __shared__ __align__(16) float s0t[32 * 36];
    __shared__ __align__(16) float s1t[32 * 68];
    __shared__ __align__(16) float s2t[32 * 100];
    __shared__ __align__(16) float mb[8][200];

    int t = threadIdx.x;
    for (int i = t; i < 1024; i += blockDim.x) { int k = i / 32, w = i % 32; s0t[w * 36 + k]  = l2_0[i]; }
    for (int i = t; i < 2048; i += blockDim.x) { int k = i / 32, w = i % 32; s1t[w * 68 + k]  = l2_1[i]; }
    for (int i = t; i < 3072; i += blockDim.x) { int k = i / 32, w = i % 32; s2t[w * 100 + k] = l2_2[i]; }
    __syncthreads();

    int lane = t & 31;
    int wrp  = t >> 5;
    int n0 = (blockIdx.x * 8 + wrp) * 2;
    float* m = mb[wrp];

    m[lane]       = g_mid[n0 * 96 + lane];
    m[32 + lane]  = g_mid[n0 * 96 + 32 + lane];
    m[64 + lane]  = g_mid[n0 * 96 + 64 + lane];
    m[96 + lane]  = g_mid[(n0 + 1) * 96 + lane];
    m[128 + lane] = g_mid[(n0 + 1) * 96 + 32 + lane];
    m[160 + lane] = g_mid[(n0 + 1) * 96 + 64 + lane];
    __syncwarp();

    unsigned long long A0a = 0ull, A1a = 0ull, A2a = 0ull, B2a = 0ull;
    unsigned long long A0b = 0ull, A1b = 0ull, A2b = 0ull, B2b = 0ull;
    const float* p0 = &s0t[lane * 36];
    const float* p1 = &s1t[lane * 68];
    const float* p2 = &s2t[lane * 100];
#pragma unroll
    for (int c = 0; c < 24; c++) {
        int k = c * 4;
        ulonglong2 ma = *(const ulonglong2*)&m[k];
        ulonglong2 mv = *(const ulonglong2*)&m[96 + k];
        ulonglong2 q2 = *(const ulonglong2*)(p2 + k);
        A2a = fma2(ma.x, q2.x, A2a);
        B2a = fma2(ma.y, q2.y, B2a);
        A2b = fma2(mv.x, q2.x, A2b);
        B2b = fma2(mv.y, q2.y, B2b);
        if (c < 16) {
            ulonglong2 q1 = *(const ulonglong2*)(p1 + k);
            A1a = fma2(ma.x, q1.x, A1a);
            A1a = fma2(ma.y, q1.y, A1a);
            A1b = fma2(mv.x, q1.x, A1b);
            A1b = fma2(mv.y, q1.y, A1b);
        }
        if (c < 8) {
            ulonglong2 q0 = *(const ulonglong2*)(p0 + k);
            A0a = fma2(ma.x, q0.x, A0a);
            A0a = fma2(ma.y, q0.y, A0a);
            A0b = fma2(mv.x, q0.x, A0b);
            A0b = fma2(mv.y, q0.y, A0b);
        }
    }

    const float i32 = 0.17677669529663687f;
    const float i64 = 0.125f;
    const float i96 = 0.10206207261596575f;

    float lo, hi, v0a, v1a, v2a, v0b, v1b, v2b;
    asm("mov.b64 {%0,%1}, %2;" : "=f"(lo), "=f"(hi) : "l"(A0a)); v0a = lo + hi;
    asm("mov.b64 {%0,%1}, %2;" : "=f"(lo), "=f"(hi) : "l"(A1a)); v1a = lo + hi;
    asm("mov.b64 {%0,%1}, %2;" : "=f"(lo), "=f"(hi) : "l"(A2a)); v2a = lo + hi;
    asm("mov.b64 {%0,%1}, %2;" : "=f"(lo), "=f"(hi) : "l"(B2a)); v2a += lo + hi;
    asm("mov.b64 {%0,%1}, %2;" : "=f"(lo), "=f"(hi) : "l"(A0b)); v0b = lo + hi;
    asm("mov.b64 {%0,%1}, %2;" : "=f"(lo), "=f"(hi) : "l"(A1b)); v1b = lo + hi;
    asm("mov.b64 {%0,%1}, %2;" : "=f"(lo), "=f"(hi) : "l"(A2b)); v2b = lo + hi;
    asm("mov.b64 {%0,%1}, %2;" : "=f"(lo), "=f"(hi) : "l"(B2b)); v2b += lo + hi;

    out[                    n0 * 32 + lane]       = silu_f(fmaf(v0a, i32, g_sc[                   n0 * 32 + lane]));
    out[N_NODES * 32      + n0 * 32 + lane]       = silu_f(fmaf(v1a, i64, g_sc[N_NODES * 32     + n0 * 32 + lane]));
    out[2 * N_NODES * 32  + n0 * 32 + lane]       = silu_f(fmaf(v2a, i96, g_sc[2 * N_NODES * 32 + n0 * 32 + lane]));
    out[                    (n0 + 1) * 32 + lane] = silu_f(fmaf(v0b, i32, g_sc[                   (n0 + 1) * 32 + lane]));
    out[N_NODES * 32      + (n0 + 1) * 32 + lane] = silu_f(fmaf(v1b, i64, g_sc[N_NODES * 32     + (n0 + 1) * 32 + lane]));
    out[2 * N_NODES * 32  + (n0 + 1) * 32 + lane] = silu_f(fmaf(v2b, i96, g_sc[2 * N_NODES * 32 + (n0 + 1) * 32 + lane]));
}

// ---------------- launch ----------------
extern "C" void kernel_launch(void* const* d_in, const int* in_sizes, int n_in,
                              void* d_out, int out_size)
{
    const float* x      = (const float*)d_in[0];
    const float* na     = (const float*)d_in[1];
    const float* ee     = (const float*)d_in[2];
    const float* ea     = (const float*)d_in[3];
    const int*   eidx   = (const int*)  d_in[4];
    const float* W1_0   = (const float*)d_in[5];
    const float* W1_1   = (const float*)d_in[6];
    const float* W1_2   = (const float*)d_in[7];
    const float* Wm0    = (const float*)d_in[8];
    const float* Wm1    = (const float*)d_in[9];
    const float* l2_0   = (const float*)d_in[10];
    const float* l2_1   = (const float*)d_in[11];
    const float* l2_2   = (const float*)d_in[12];
    const float* scW    = (const float*)d_in[13];
    float* out = (float*)d_out;

    cudaFuncSetAttribute(k1_kernel, cudaFuncAttributeMaxDynamicSharedMemorySize, 49152);
    cudaFuncSetAttribute(k2_kernel, cudaFuncAttributeMaxDynamicSharedMemorySize, K2_SMEM);

    // launch order chosen so k2 is the 4th kernel launch (profiler capture slot)
    k1_kernel<<<1875, 256, 49152>>>(x, na, W1_0, W1_1, W1_2, scW);
    noop_kernel<<<1, 32>>>();
    noop_kernel<<<1, 32>>>();
    k2_kernel<<<K2_BLOCKS, 128, K2_SMEM>>>(ee, ea, eidx, Wm0, Wm1);
    k3_kernel<<<1250, 256>>>(l2_0, l2_1, l2_2, out);
    (void)in_sizes; (void)n_in; (void)out_size;
}